// round 4
// baseline (speedup 1.0000x reference)
#include <cuda_runtime.h>
#include <math.h>
#include <stdint.h>

#define B_  512
#define S_  200
#define H_  256
#define K_  16
#define ROWS (B_*S_)          // 102400
#define TM  128               // rows per CTA
#define NBLK (ROWS/TM)        // 800

// smem word layout (kernel 1)
#define AST  260              // A row stride (words); 260 % 32 == 4
#define CBST 36               // W-chunk row stride (words); 36 % 32 == 4
#define A_WORDS  (128*AST)                // 33280
#define BC_OFF   A_WORDS                  // two chunk bufs, 256*36 words each
#define BC_ONE   (256*CBST)               // 9216
#define W3_OFF   (BC_OFF + 2*BC_ONE)      // 51712
#define W3ST 260
#define SM_WORDS (W3_OFF + 16*W3ST)       // 55872
#define SM_BYTES (SM_WORDS*4)             // 223488

// scratch
__device__ float    g_A[ROWS * K_];        // masked K-softmax logits
__device__ uint32_t g_Wt[2 * 65536];       // W1,W2 tf32, chunk-linear [l][c][n][kl]
__device__ uint32_t g_Wt3[16 * 256];       // W3 tf32, [n][k]

__device__ __forceinline__ uint32_t smem_u32(const void* p) {
    uint32_t a;
    asm("{ .reg .u64 t; cvta.to.shared.u64 t, %1; cvt.u32.u64 %0, t; }"
        : "=r"(a) : "l"(p));
    return a;
}
__device__ __forceinline__ uint32_t f2tf32(float x) {   // round-to-nearest tf32
    uint32_t r; asm("cvt.rna.tf32.f32 %0, %1;" : "=r"(r) : "f"(x)); return r;
}
__device__ __forceinline__ void mma8(float c[4], const uint32_t a[4],
                                     uint32_t b0, uint32_t b1) {
    asm("mma.sync.aligned.m16n8k8.row.col.f32.tf32.tf32.f32 "
        "{%0,%1,%2,%3}, {%4,%5,%6,%7}, {%8,%9}, {%0,%1,%2,%3};"
        : "+f"(c[0]), "+f"(c[1]), "+f"(c[2]), "+f"(c[3])
        : "r"(a[0]), "r"(a[1]), "r"(a[2]), "r"(a[3]), "r"(b0), "r"(b1));
}
__device__ __forceinline__ void cpasync16(uint32_t dst, const void* src) {
    asm volatile("cp.async.cg.shared.global [%0], [%1], 16;" :: "r"(dst), "l"(src));
}
#define CP_COMMIT() asm volatile("cp.async.commit_group;" ::: "memory")
#define CP_WAIT0()  asm volatile("cp.async.wait_group 0;" ::: "memory")

// ---------------------------------------------------------------------------
// Prep: convert weights to tf32 into cp.async-friendly layouts (runs once/launch)
// g_Wt[l][c][n][kl] = tf32(W[l][32c+kl][n]) ; g_Wt3[n][k] = tf32(W3[k][n])
// ---------------------------------------------------------------------------
__global__ void prep_kernel(const float* __restrict__ W1,
                            const float* __restrict__ W2,
                            const float* __restrict__ W3)
{
    const int idx = blockIdx.x * 256 + threadIdx.x;
    if (idx < 32768) {
        const int layer = idx >> 14;
        const int rem   = idx & 16383;
        const int k     = rem >> 6;
        const int n0    = (rem & 63) << 2;
        const float* W  = layer ? W2 : W1;
        const float4 v  = *(const float4*)(W + (size_t)k * H_ + n0);
        uint32_t* dst = g_Wt + layer * 65536 + (k >> 5) * 8192 + (k & 31);
        dst[(size_t)(n0 + 0) * 32] = f2tf32(v.x);
        dst[(size_t)(n0 + 1) * 32] = f2tf32(v.y);
        dst[(size_t)(n0 + 2) * 32] = f2tf32(v.z);
        dst[(size_t)(n0 + 3) * 32] = f2tf32(v.w);
    } else if (idx < 32768 + 1024) {
        const int rem = idx - 32768;
        const int k   = rem >> 2;
        const int n0  = (rem & 3) << 2;
        const float4 v = *(const float4*)(W3 + (size_t)k * K_ + n0);
        g_Wt3[(size_t)(n0 + 0) * 256 + k] = f2tf32(v.x);
        g_Wt3[(size_t)(n0 + 1) * 256 + k] = f2tf32(v.y);
        g_Wt3[(size_t)(n0 + 2) * 256 + k] = f2tf32(v.z);
        g_Wt3[(size_t)(n0 + 3) * 256 + k] = f2tf32(v.w);
    }
}

// ---------------------------------------------------------------------------
// Kernel 1: tf32 mma.sync MLP with cp.async double-buffered W chunks
// grid = 800, block = 256 (8 warps; warp grid 2(M) x 4(N))
// ---------------------------------------------------------------------------
__device__ __forceinline__ void prefetch_chunk(uint32_t sb, int tid,
                                               int layer, int cc, int buf) {
    const uint32_t* src = g_Wt + layer * 65536 + cc * 8192 + tid * 32;
    const uint32_t  dst = sb + (uint32_t)(BC_OFF + buf * BC_ONE + tid * CBST) * 4;
    #pragma unroll
    for (int j = 0; j < 8; j++) cpasync16(dst + j * 16, src + j * 4);
}
__device__ __forceinline__ void prefetch_w3(uint32_t sb, int tid) {
    #pragma unroll
    for (int q = 0; q < 4; q++) {
        const int i = tid * 4 + q;
        const int n = i >> 6, kk = (i & 63) * 4;
        cpasync16(sb + (uint32_t)(W3_OFF + n * W3ST + kk) * 4, g_Wt3 + (size_t)i * 4);
    }
}

__global__ __launch_bounds__(256, 1)
void mlp_softk_kernel(const float* __restrict__ X,
                      const int*   __restrict__ mask,
                      const float* __restrict__ b1,
                      const float* __restrict__ b2)
{
    extern __shared__ uint32_t smu[];
    const uint32_t sb = smem_u32(smu);
    const int tid  = threadIdx.x;
    const int wid  = tid >> 5;
    const int lane = tid & 31;
    const int g    = lane >> 2;
    const int tq   = lane & 3;
    const int row0 = blockIdx.x * TM;

    // kick off W chunk (0,0) copy, then load X tile under it
    prefetch_chunk(sb, tid, 0, 0, 0);
    CP_COMMIT();

    #pragma unroll 4
    for (int it = 0; it < 32; it++) {
        const int idx = tid + it * 256;
        const int r = idx >> 6, c4 = (idx & 63) * 4;
        const float4 v = __ldg((const float4*)(X + (size_t)(row0 + r) * H_ + c4));
        uint4 o;
        o.x = f2tf32(v.x); o.y = f2tf32(v.y); o.z = f2tf32(v.z); o.w = f2tf32(v.w);
        *(uint4*)&smu[r * AST + c4] = o;
    }

    const int wm = wid & 1;        // M block: rows wm*64 .. +63
    const int wn = wid >> 1;       // N block: cols wn*64 .. +63

    #pragma unroll 1
    for (int layer = 0; layer < 2; layer++) {
        const float* bg = layer ? b2 : b1;

        float acc[4][8][4];
        #pragma unroll
        for (int mt = 0; mt < 4; mt++)
            #pragma unroll
            for (int n8 = 0; n8 < 8; n8++)
                #pragma unroll
                for (int i = 0; i < 4; i++) acc[mt][n8][i] = 0.0f;

        #pragma unroll 1
        for (int cc = 0; cc < 8; cc++) {
            CP_WAIT0();
            __syncthreads();     // chunk cc visible; all mma of cc-1 finished

            // prefetch next buffer while we compute on this one
            if (layer == 1 && cc == 7) prefetch_w3(sb, tid);
            else {
                const int nl = (cc == 7) ? 1  : layer;
                const int nc = (cc == 7) ? 0  : cc + 1;
                prefetch_chunk(sb, tid, nl, nc, (cc + 1) & 1);
            }
            CP_COMMIT();

            const uint32_t* Bb = smu + BC_OFF + (cc & 1) * BC_ONE;
            #pragma unroll
            for (int ks = 0; ks < 4; ks++) {
                const int k0 = cc * 32 + ks * 8;
                const int kl = ks * 8;
                uint32_t a[4][4];
                #pragma unroll
                for (int mt = 0; mt < 4; mt++) {
                    const int r = wm * 64 + mt * 16 + g;
                    a[mt][0] = smu[(r    ) * AST + k0 + tq];
                    a[mt][1] = smu[(r + 8) * AST + k0 + tq];
                    a[mt][2] = smu[(r    ) * AST + k0 + tq + 4];
                    a[mt][3] = smu[(r + 8) * AST + k0 + tq + 4];
                }
                #pragma unroll
                for (int n8 = 0; n8 < 8; n8++) {
                    const int n = wn * 64 + n8 * 8 + g;
                    const uint32_t b0 = Bb[n * CBST + kl + tq];
                    const uint32_t b1v = Bb[n * CBST + kl + tq + 4];
                    #pragma unroll
                    for (int mt = 0; mt < 4; mt++) mma8(acc[mt][n8], a[mt], b0, b1v);
                }
            }
        }
        __syncthreads();   // all mma reads of A done -> safe to overwrite A

        // epilogue: bias + relu + tf32 -> A
        #pragma unroll
        for (int mt = 0; mt < 4; mt++) {
            const int r = wm * 64 + mt * 16 + g;
            #pragma unroll
            for (int n8 = 0; n8 < 8; n8++) {
                const int c = wn * 64 + n8 * 8 + 2 * tq;
                const float2 bb = *(const float2*)&bg[c];
                uint2 o0, o1;
                o0.x = f2tf32(fmaxf(acc[mt][n8][0] + bb.x, 0.f));
                o0.y = f2tf32(fmaxf(acc[mt][n8][1] + bb.y, 0.f));
                o1.x = f2tf32(fmaxf(acc[mt][n8][2] + bb.x, 0.f));
                o1.y = f2tf32(fmaxf(acc[mt][n8][3] + bb.y, 0.f));
                *(uint2*)&smu[(r    ) * AST + c] = o0;
                *(uint2*)&smu[(r + 8) * AST + c] = o1;
            }
        }
    }

    CP_WAIT0();
    __syncthreads();     // W3 in smem; layer-2 epilogue visible

    // ---- layer 3: logits = h2 @ W3 (each warp: 16 rows) ----
    float acc3[2][4];
    #pragma unroll
    for (int n8 = 0; n8 < 2; n8++)
        #pragma unroll
        for (int i = 0; i < 4; i++) acc3[n8][i] = 0.0f;

    {
        const uint32_t* Bu3 = smu + W3_OFF;
        const int r = wid * 16 + g;
        #pragma unroll 4
        for (int ks = 0; ks < 32; ks++) {
            const int k0 = ks * 8;
            uint32_t a[4];
            a[0] = smu[(r    ) * AST + k0 + tq];
            a[1] = smu[(r + 8) * AST + k0 + tq];
            a[2] = smu[(r    ) * AST + k0 + tq + 4];
            a[3] = smu[(r + 8) * AST + k0 + tq + 4];
            #pragma unroll
            for (int n8 = 0; n8 < 2; n8++) {
                const uint32_t b0 = Bu3[(n8 * 8 + g) * W3ST + k0 + tq];
                const uint32_t b1v = Bu3[(n8 * 8 + g) * W3ST + k0 + tq + 4];
                mma8(acc3[n8], a, b0, b1v);
            }
        }
    }

    // ---- softmax over K=16 per row, mask, /4, store ----
    #pragma unroll
    for (int p = 0; p < 2; p++) {
        const int row = row0 + wid * 16 + g + p * 8;
        float v0 = acc3[0][2 * p], v1 = acc3[0][2 * p + 1];
        float v2 = acc3[1][2 * p], v3 = acc3[1][2 * p + 1];
        float m = fmaxf(fmaxf(v0, v1), fmaxf(v2, v3));
        m = fmaxf(m, __shfl_xor_sync(0xffffffffu, m, 1));
        m = fmaxf(m, __shfl_xor_sync(0xffffffffu, m, 2));
        const float e0 = expf(v0 - m), e1 = expf(v1 - m);
        const float e2 = expf(v2 - m), e3 = expf(v3 - m);
        float ssum = e0 + e1 + e2 + e3;
        ssum += __shfl_xor_sync(0xffffffffu, ssum, 1);
        ssum += __shfl_xor_sync(0xffffffffu, ssum, 2);
        const float inv = 0.25f / ssum;             // includes /sqrt(K) = /4
        const bool mk = (mask[row] != 0);
        float2 oa, ob;
        oa.x = mk ? e0 * inv : -2500.0f;            // -10000/4
        oa.y = mk ? e1 * inv : -2500.0f;
        ob.x = mk ? e2 * inv : -2500.0f;
        ob.y = mk ? e3 * inv : -2500.0f;
        *(float2*)&g_A[(size_t)row * K_ + 2 * tq]     = oa;
        *(float2*)&g_A[(size_t)row * K_ + 8 + 2 * tq] = ob;
    }
}

// ---------------------------------------------------------------------------
// Kernel 2: softmax over S per (b,k), * time factor, out[b,k,h] = sum_s X*D
// grid = 512 (one block per batch), 256 threads (thread = h), f32x2 FMA.
// ---------------------------------------------------------------------------
__device__ __forceinline__ void fma2(unsigned long long& a,
                                     unsigned long long x, unsigned long long d) {
    asm("fma.rn.f32x2 %0, %1, %2, %0;" : "+l"(a) : "l"(x), "l"(d));
}

__global__ __launch_bounds__(256, 4)
void softs_out_kernel(const float* __restrict__ X,
                      const float* __restrict__ tf,
                      float*       __restrict__ out)
{
    __shared__ __align__(16) float As[S_ * K_];   // 12.8 KB
    __shared__ float Tf[S_];
    __shared__ float Mk[K_], Ik[K_];

    const int b   = blockIdx.x;
    const int tid = threadIdx.x;

    for (int idx = tid; idx < S_ * K_; idx += 256)
        As[idx] = g_A[(size_t)b * S_ * K_ + idx];
    for (int idx = tid; idx < S_; idx += 256)
        Tf[idx] = tf[b * S_ + idx];
    __syncthreads();

    const int warp = tid >> 5, lane = tid & 31;
    for (int k = warp; k < K_; k += 8) {
        float m = -1e30f;
        for (int s = lane; s < S_; s += 32) m = fmaxf(m, As[s * K_ + k]);
        #pragma unroll
        for (int o = 16; o; o >>= 1) m = fmaxf(m, __shfl_xor_sync(0xffffffffu, m, o));
        float ssum = 0.0f;
        for (int s = lane; s < S_; s += 32) ssum += expf(As[s * K_ + k] - m);
        #pragma unroll
        for (int o = 16; o; o >>= 1) ssum += __shfl_xor_sync(0xffffffffu, ssum, o);
        if (lane == 0) { Mk[k] = m; Ik[k] = 1.0f / ssum; }
    }
    __syncthreads();

    for (int idx = tid; idx < S_ * K_; idx += 256) {
        const int s = idx >> 4, k = idx & 15;
        As[idx] = expf(As[idx] - Mk[k]) * Ik[k] * Tf[s];
    }
    __syncthreads();

    unsigned long long acc[8];
    #pragma unroll
    for (int i = 0; i < 8; i++) acc[i] = 0ull;

    const float* Xb = X + (size_t)b * S_ * H_ + tid;
    #pragma unroll 8
    for (int s = 0; s < S_; s++) {
        const float xv = __ldg(Xb + (size_t)s * H_);
        unsigned long long xv2;
        asm("mov.b64 %0, {%1, %1};" : "=l"(xv2) : "f"(xv));
        const unsigned long long* d = (const unsigned long long*)&As[s * K_];
        #pragma unroll
        for (int i = 0; i < 8; i++) fma2(acc[i], xv2, d[i]);
    }

    float* ob = out + (size_t)b * K_ * H_ + tid;
    #pragma unroll
    for (int i = 0; i < 8; i++) {
        float lo, hi;
        asm("mov.b64 {%0, %1}, %2;" : "=f"(lo), "=f"(hi) : "l"(acc[i]));
        ob[(size_t)(2 * i)     * H_] = lo;
        ob[(size_t)(2 * i + 1) * H_] = hi;
    }
}

// ---------------------------------------------------------------------------
extern "C" void kernel_launch(void* const* d_in, const int* in_sizes, int n_in,
                              void* d_out, int out_size)
{
    const float* X    = (const float*)d_in[0];   // (B,S,H)
    const int*   mask = (const int*)  d_in[1];   // (B,S,1)
    const float* tf   = (const float*)d_in[2];   // (B,S,1)
    const float* W1   = (const float*)d_in[3];
    const float* b1   = (const float*)d_in[4];
    const float* W2   = (const float*)d_in[5];
    const float* b2   = (const float*)d_in[6];
    const float* W3   = (const float*)d_in[7];
    float* out = (float*)d_out;                  // (B,K,H)

    cudaFuncSetAttribute(mlp_softk_kernel,
                         cudaFuncAttributeMaxDynamicSharedMemorySize, SM_BYTES);

    prep_kernel<<<132, 256>>>(W1, W2, W3);
    mlp_softk_kernel<<<NBLK, 256, SM_BYTES>>>(X, mask, b1, b2);
    softs_out_kernel<<<B_, 256>>>(X, tf, out);
}

// round 6
// speedup vs baseline: 1.5432x; 1.5432x over previous
#include <cuda_runtime.h>
#include <cuda_fp16.h>
#include <math.h>
#include <stdint.h>

#define B_  512
#define S_  200
#define H_  256
#define K_  16
#define ROWS (B_*S_)          // 102400
#define TM  128               // rows per CTA
#define NBLK (ROWS/TM)        // 800

// smem layout in 32-bit words (kernel 1); all fp16 data, 2 fp16 per word
#define ASTW  132             // A row stride (words) = 264 fp16; 132 % 32 == 4
#define CBSTW 36              // W-chunk row stride (words) = 72 fp16; 36 % 32 == 4
#define A_WORDS  (128*ASTW)               // 16896
#define BC_OFF   A_WORDS
#define BC_ONE   (256*CBSTW)              // 9216
#define W3_OFF   (BC_OFF + 2*BC_ONE)      // 35328
#define W3STW 132
#define SM_WORDS (W3_OFF + 16*W3STW)      // 37440
#define SM_BYTES (SM_WORDS*4)             // 149760

// scratch
__device__ float    g_A[ROWS * K_];          // masked K-softmax logits
__device__ uint32_t g_Wh[2 * 32768];         // W1,W2 fp16 [l][c4][n256][kl64]
__device__ uint32_t g_Wh3[16 * 128];         // W3 fp16 [n16][k256]

__device__ __forceinline__ uint32_t smem_u32(const void* p) {
    uint32_t a;
    asm("{ .reg .u64 t; cvta.to.shared.u64 t, %1; cvt.u32.u64 %0, t; }"
        : "=r"(a) : "l"(p));
    return a;
}
__device__ __forceinline__ uint32_t pack_h2(float lo, float hi) {
    const __half2 h = __floats2half2_rn(lo, hi);   // x=lo, y=hi
    return *(const uint32_t*)&h;
}
// fp16 MMA, f32 accumulate: D(16x8) += A(16x16,row) * B(16x8,col)
__device__ __forceinline__ void mma16(float c[4], const uint32_t a[4],
                                      uint32_t b0, uint32_t b1) {
    asm("mma.sync.aligned.m16n8k16.row.col.f32.f16.f16.f32 "
        "{%0,%1,%2,%3}, {%4,%5,%6,%7}, {%8,%9}, {%0,%1,%2,%3};"
        : "+f"(c[0]), "+f"(c[1]), "+f"(c[2]), "+f"(c[3])
        : "r"(a[0]), "r"(a[1]), "r"(a[2]), "r"(a[3]), "r"(b0), "r"(b1));
}
__device__ __forceinline__ void cpasync16(uint32_t dst, const void* src) {
    asm volatile("cp.async.cg.shared.global [%0], [%1], 16;" :: "r"(dst), "l"(src));
}
#define CP_COMMIT() asm volatile("cp.async.commit_group;" ::: "memory")
#define CP_WAIT0()  asm volatile("cp.async.wait_group 0;" ::: "memory")

// ---------------------------------------------------------------------------
// Prep: weights -> fp16, cp.async-friendly layouts
// g_Wh fp16 idx = ((l*4 + c)*256 + n)*64 + kl  holds W[l][c*64+kl][n]
// g_Wh3 fp16 idx = n*256 + k                   holds W3[k][n]
// ---------------------------------------------------------------------------
__global__ void prep_kernel(const float* __restrict__ W1,
                            const float* __restrict__ W2,
                            const float* __restrict__ W3)
{
    const int i = blockIdx.x * 256 + threadIdx.x;   // one 16B line each
    if (i < 16384) {
        const int kl8 = i & 7;
        const int n   = (i >> 3) & 255;
        const int c   = (i >> 11) & 3;
        const int l   = i >> 13;
        const float* W = l ? W2 : W1;
        const int kbase = c * 64 + kl8 * 8;
        uint4 o;
        o.x = pack_h2(W[(size_t)(kbase+0)*H_ + n], W[(size_t)(kbase+1)*H_ + n]);
        o.y = pack_h2(W[(size_t)(kbase+2)*H_ + n], W[(size_t)(kbase+3)*H_ + n]);
        o.z = pack_h2(W[(size_t)(kbase+4)*H_ + n], W[(size_t)(kbase+5)*H_ + n]);
        o.w = pack_h2(W[(size_t)(kbase+6)*H_ + n], W[(size_t)(kbase+7)*H_ + n]);
        *(uint4*)&g_Wh[(size_t)i * 4] = o;
    } else if (i < 16384 + 512) {
        const int j  = i - 16384;
        const int n  = j >> 5;
        const int k8 = (j & 31) * 8;
        uint4 o;
        o.x = pack_h2(W3[(size_t)(k8+0)*K_ + n], W3[(size_t)(k8+1)*K_ + n]);
        o.y = pack_h2(W3[(size_t)(k8+2)*K_ + n], W3[(size_t)(k8+3)*K_ + n]);
        o.z = pack_h2(W3[(size_t)(k8+4)*K_ + n], W3[(size_t)(k8+5)*K_ + n]);
        o.w = pack_h2(W3[(size_t)(k8+6)*K_ + n], W3[(size_t)(k8+7)*K_ + n]);
        *(uint4*)&g_Wh3[(size_t)j * 4] = o;
    }
}

// ---------------------------------------------------------------------------
// Kernel 1: fp16 mma.sync MLP, cp.async double-buffered W chunks (K=64)
// grid = 800, block = 256 (8 warps; warp grid 4(M) x 2(N))
// ---------------------------------------------------------------------------
__device__ __forceinline__ void prefetch_chunk(uint32_t sb, int tid,
                                               int layer, int cc, int buf) {
    const uint32_t* src = g_Wh + (size_t)(layer * 4 + cc) * 8192 + tid * 32;
    const uint32_t  dst = sb + (uint32_t)(BC_OFF + buf * BC_ONE + tid * CBSTW) * 4;
    #pragma unroll
    for (int j = 0; j < 8; j++) cpasync16(dst + j * 16, src + j * 4);
}
__device__ __forceinline__ void prefetch_w3(uint32_t sb, int tid) {
    #pragma unroll
    for (int q = 0; q < 2; q++) {
        const int i = tid * 2 + q;
        const int n = i >> 5, kk = i & 31;
        cpasync16(sb + (uint32_t)(W3_OFF + n * W3STW + kk * 4) * 4,
                  g_Wh3 + (size_t)i * 4);
    }
}

__global__ __launch_bounds__(256, 1)
void mlp_softk_kernel(const float* __restrict__ X,
                      const int*   __restrict__ mask,
                      const float* __restrict__ b1,
                      const float* __restrict__ b2)
{
    extern __shared__ uint32_t smu[];
    const uint32_t sb = smem_u32(smu);
    const int tid  = threadIdx.x;
    const int wid  = tid >> 5;
    const int lane = tid & 31;
    const int g    = lane >> 2;
    const int tq   = lane & 3;
    const int row0 = blockIdx.x * TM;

    prefetch_chunk(sb, tid, 0, 0, 0);
    CP_COMMIT();

    // X tile -> A (fp16). thread: row r, 4 cols c4..c4+3 -> 2 words
    #pragma unroll 4
    for (int it = 0; it < 32; it++) {
        const int idx = tid + it * 256;
        const int r = idx >> 6, c4 = (idx & 63) * 4;
        const float4 v = __ldg((const float4*)(X + (size_t)(row0 + r) * H_ + c4));
        uint2 o;
        o.x = pack_h2(v.x, v.y);
        o.y = pack_h2(v.z, v.w);
        *(uint2*)&smu[r * ASTW + (c4 >> 1)] = o;
    }

    const int wm = wid & 3;        // M block: rows wm*32 .. +31
    const int wn = wid >> 2;       // N half:  cols wn*128 .. +127

    #pragma unroll 1
    for (int layer = 0; layer < 2; layer++) {
        const float* bg = layer ? b2 : b1;

        float acc[2][16][4];
        #pragma unroll
        for (int mt = 0; mt < 2; mt++)
            #pragma unroll
            for (int n8 = 0; n8 < 16; n8++)
                #pragma unroll
                for (int i = 0; i < 4; i++) acc[mt][n8][i] = 0.0f;

        #pragma unroll 1
        for (int cc = 0; cc < 4; cc++) {
            CP_WAIT0();
            __syncthreads();     // chunk cc landed; mma reads of cc-1 done

            if (layer == 1 && cc == 3) prefetch_w3(sb, tid);
            else {
                const int nl = (cc == 3) ? 1 : layer;
                const int nc = (cc == 3) ? 0 : cc + 1;
                prefetch_chunk(sb, tid, nl, nc, (cc + 1) & 1);
            }
            CP_COMMIT();

            const uint32_t* Bb = smu + BC_OFF + (cc & 1) * BC_ONE;
            #pragma unroll
            for (int ks = 0; ks < 4; ks++) {               // k-step of 16
                const int k0 = cc * 64 + ks * 16;          // global k
                const int kw = k0 >> 1;                    // word col in A
                const int klw = (ks * 16) >> 1;            // word col in B chunk
                uint32_t a[2][4];
                #pragma unroll
                for (int mt = 0; mt < 2; mt++) {
                    const int r = wm * 32 + mt * 16 + g;
                    a[mt][0] = smu[(r    ) * ASTW + kw + tq];
                    a[mt][1] = smu[(r + 8) * ASTW + kw + tq];
                    a[mt][2] = smu[(r    ) * ASTW + kw + tq + 4];
                    a[mt][3] = smu[(r + 8) * ASTW + kw + tq + 4];
                }
                #pragma unroll
                for (int n8 = 0; n8 < 16; n8++) {
                    const int n = wn * 128 + n8 * 8 + g;
                    const uint32_t b0 = Bb[n * CBSTW + klw + tq];
                    const uint32_t b1v = Bb[n * CBSTW + klw + tq + 4];
                    mma16(acc[0][n8], a[0], b0, b1v);
                    mma16(acc[1][n8], a[1], b0, b1v);
                }
            }
        }
        __syncthreads();   // all mma reads of A done -> safe to overwrite A

        // epilogue: bias + relu -> fp16 -> A
        #pragma unroll
        for (int mt = 0; mt < 2; mt++) {
            const int r = wm * 32 + mt * 16 + g;
            #pragma unroll
            for (int n8 = 0; n8 < 16; n8++) {
                const int c = wn * 128 + n8 * 8 + 2 * tq;
                const float2 bb = *(const float2*)&bg[c];
                smu[(r    ) * ASTW + (c >> 1)] =
                    pack_h2(fmaxf(acc[mt][n8][0] + bb.x, 0.f),
                            fmaxf(acc[mt][n8][1] + bb.y, 0.f));
                smu[(r + 8) * ASTW + (c >> 1)] =
                    pack_h2(fmaxf(acc[mt][n8][2] + bb.x, 0.f),
                            fmaxf(acc[mt][n8][3] + bb.y, 0.f));
            }
        }
    }

    CP_WAIT0();
    __syncthreads();     // W3 in smem; layer-2 epilogue visible

    // ---- layer 3: logits = h2 @ W3 (each warp: 16 rows) ----
    float acc3[2][4];
    #pragma unroll
    for (int n8 = 0; n8 < 2; n8++)
        #pragma unroll
        for (int i = 0; i < 4; i++) acc3[n8][i] = 0.0f;

    {
        const uint32_t* Bu3 = smu + W3_OFF;
        const int r = wid * 16 + g;
        #pragma unroll 4
        for (int ks = 0; ks < 16; ks++) {
            const int kw = ks * 8;
            uint32_t a[4];
            a[0] = smu[(r    ) * ASTW + kw + tq];
            a[1] = smu[(r + 8) * ASTW + kw + tq];
            a[2] = smu[(r    ) * ASTW + kw + tq + 4];
            a[3] = smu[(r + 8) * ASTW + kw + tq + 4];
            #pragma unroll
            for (int n8 = 0; n8 < 2; n8++) {
                const uint32_t b0 = Bu3[(n8 * 8 + g) * W3STW + kw + tq];
                const uint32_t b1v = Bu3[(n8 * 8 + g) * W3STW + kw + tq + 4];
                mma16(acc3[n8], a, b0, b1v);
            }
        }
    }

    // ---- softmax over K=16 per row, mask, /4, store ----
    #pragma unroll
    for (int p = 0; p < 2; p++) {
        const int row = row0 + wid * 16 + g + p * 8;
        float v0 = acc3[0][2 * p], v1 = acc3[0][2 * p + 1];
        float v2 = acc3[1][2 * p], v3 = acc3[1][2 * p + 1];
        float m = fmaxf(fmaxf(v0, v1), fmaxf(v2, v3));
        m = fmaxf(m, __shfl_xor_sync(0xffffffffu, m, 1));
        m = fmaxf(m, __shfl_xor_sync(0xffffffffu, m, 2));
        const float e0 = expf(v0 - m), e1 = expf(v1 - m);
        const float e2 = expf(v2 - m), e3 = expf(v3 - m);
        float ssum = e0 + e1 + e2 + e3;
        ssum += __shfl_xor_sync(0xffffffffu, ssum, 1);
        ssum += __shfl_xor_sync(0xffffffffu, ssum, 2);
        const float inv = 0.25f / ssum;             // includes /sqrt(K) = /4
        const bool mk = (mask[row] != 0);
        float2 oa, ob;
        oa.x = mk ? e0 * inv : -2500.0f;            // -10000/4
        oa.y = mk ? e1 * inv : -2500.0f;
        ob.x = mk ? e2 * inv : -2500.0f;
        ob.y = mk ? e3 * inv : -2500.0f;
        *(float2*)&g_A[(size_t)row * K_ + 2 * tq]     = oa;
        *(float2*)&g_A[(size_t)row * K_ + 8 + 2 * tq] = ob;
    }
}

// ---------------------------------------------------------------------------
// Kernel 2: softmax over S per (b,k), * time factor, out[b,k,h] = sum_s X*D
// grid = (512, 2); f32x2 packed FMA. (round-3 version, measured 54.6us)
// ---------------------------------------------------------------------------
__device__ __forceinline__ void fma2(unsigned long long& a,
                                     unsigned long long x, unsigned long long d) {
    asm("fma.rn.f32x2 %0, %1, %2, %0;" : "+l"(a) : "l"(x), "l"(d));
}

__global__ __launch_bounds__(128, 8)
void softs_out_kernel(const float* __restrict__ X,
                      const float* __restrict__ tf,
                      float*       __restrict__ out)
{
    __shared__ __align__(16) float As[S_ * K_];   // 12.8 KB
    __shared__ float Tf[S_];
    __shared__ float Mk[K_], Ik[K_];

    const int b   = blockIdx.x;
    const int hb  = blockIdx.y;
    const int tid = threadIdx.x;

    for (int idx = tid; idx < S_ * K_; idx += 128)
        As[idx] = g_A[(size_t)b * S_ * K_ + idx];
    for (int idx = tid; idx < S_; idx += 128)
        Tf[idx] = tf[b * S_ + idx];
    __syncthreads();

    const int warp = tid >> 5, lane = tid & 31;
    for (int k = warp; k < K_; k += 4) {
        float m = -1e30f;
        for (int s = lane; s < S_; s += 32) m = fmaxf(m, As[s * K_ + k]);
        #pragma unroll
        for (int o = 16; o; o >>= 1) m = fmaxf(m, __shfl_xor_sync(0xffffffffu, m, o));
        float ssum = 0.0f;
        for (int s = lane; s < S_; s += 32) ssum += expf(As[s * K_ + k] - m);
        #pragma unroll
        for (int o = 16; o; o >>= 1) ssum += __shfl_xor_sync(0xffffffffu, ssum, o);
        if (lane == 0) { Mk[k] = m; Ik[k] = 1.0f / ssum; }
    }
    __syncthreads();

    for (int idx = tid; idx < S_ * K_; idx += 128) {
        const int s = idx >> 4, k = idx & 15;
        As[idx] = expf(As[idx] - Mk[k]) * Ik[k] * Tf[s];
    }
    __syncthreads();

    const int h = hb * 128 + tid;
    unsigned long long acc[8];
    #pragma unroll
    for (int i = 0; i < 8; i++) acc[i] = 0ull;

    const float* Xb = X + (size_t)b * S_ * H_ + h;
    #pragma unroll 4
    for (int s = 0; s < S_; s++) {
        const float xv = __ldg(Xb + (size_t)s * H_);
        unsigned long long xv2;
        asm("mov.b64 %0, {%1, %1};" : "=l"(xv2) : "f"(xv));
        const unsigned long long* d = (const unsigned long long*)&As[s * K_];
        #pragma unroll
        for (int i = 0; i < 8; i++) fma2(acc[i], xv2, d[i]);
    }

    float* ob = out + (size_t)b * K_ * H_ + h;
    #pragma unroll
    for (int i = 0; i < 8; i++) {
        float lo, hi;
        asm("mov.b64 {%0, %1}, %2;" : "=f"(lo), "=f"(hi) : "l"(acc[i]));
        ob[(size_t)(2 * i)     * H_] = lo;
        ob[(size_t)(2 * i + 1) * H_] = hi;
    }
}

// ---------------------------------------------------------------------------
extern "C" void kernel_launch(void* const* d_in, const int* in_sizes, int n_in,
                              void* d_out, int out_size)
{
    const float* X    = (const float*)d_in[0];   // (B,S,H)
    const int*   mask = (const int*)  d_in[1];   // (B,S,1)
    const float* tf   = (const float*)d_in[2];   // (B,S,1)
    const float* W1   = (const float*)d_in[3];
    const float* b1   = (const float*)d_in[4];
    const float* W2   = (const float*)d_in[5];
    const float* b2   = (const float*)d_in[6];
    const float* W3   = (const float*)d_in[7];
    float* out = (float*)d_out;                  // (B,K,H)

    cudaFuncSetAttribute(mlp_softk_kernel,
                         cudaFuncAttributeMaxDynamicSharedMemorySize, SM_BYTES);

    prep_kernel<<<66, 256>>>(W1, W2, W3);
    mlp_softk_kernel<<<NBLK, 256, SM_BYTES>>>(X, mask, b1, b2);
    softs_out_kernel<<<dim3(B_, 2), 128>>>(X, tf, out);
}